// round 5
// baseline (speedup 1.0000x reference)
#include <cuda_runtime.h>
#include <cuda_bf16.h>
#include <cstdint>

namespace {
constexpr int H  = 16;
constexpr int D  = 1024;
constexpr int DK = 64;
constexpr int DV = 64;
constexpr int B  = 4;
constexpr int SQ = 1024;
constexpr int SK = 1024;
constexpr float INV_SCALE = 1.0f / 32.0f;   // 1/sqrt(1024)

constexpr int KC  = 64;      // K-chunk (elements)
constexpr int KSE = 72;      // smem row stride in elements (pad 8: 36 banks ≡ 4 mod 32 → conflict-free frags)
constexpr int ATILE = 128 * KSE * 2;   // bytes per 128-row buffer (18432)
constexpr int BTILE64 = 64 * KSE * 2;  // bytes per 64-row buffer (9216)
constexpr int SMEM_BIG = 4 * ATILE;            // proj/scores/outproj: Ahi,Alo,Bhi,Blo (73728)
constexpr int SMEM_AV  = 2 * ATILE + 2 * BTILE64;  // av (55296)
}

// Scratch (allocation-free rule: __device__ globals)
__device__ float g_q[B * H * SQ * DK];      // [(b*H+h)][s][k]
__device__ float g_k[B * H * SK * DK];
__device__ float g_v[B * H * SK * DV];
__device__ float g_ctx[B * SQ * H * DV];    // [b][q][h][v]

// ---------------------------------------------------------------------------
// MMA + split helpers
// ---------------------------------------------------------------------------
__device__ __forceinline__ void mma_bf16(float* c, const uint32_t* a, const uint32_t* b) {
  asm volatile(
      "mma.sync.aligned.m16n8k16.row.col.f32.bf16.bf16.f32 "
      "{%0,%1,%2,%3}, {%4,%5,%6,%7}, {%8,%9}, {%0,%1,%2,%3};"
      : "+f"(c[0]), "+f"(c[1]), "+f"(c[2]), "+f"(c[3])
      : "r"(a[0]), "r"(a[1]), "r"(a[2]), "r"(a[3]), "r"(b[0]), "r"(b[1]));
}

__device__ __forceinline__ void split2(float x, unsigned short& h, unsigned short& l) {
  __nv_bfloat16 bh = __float2bfloat16(x);
  h = __bfloat16_as_ushort(bh);
  l = __bfloat16_as_ushort(__float2bfloat16(x - __bfloat162float(bh)));
}

// store float4 (k positions kq..kq+3, kq%4==0) into hi/lo padded tiles
__device__ __forceinline__ void store_f4p(__nv_bfloat16* hi, __nv_bfloat16* lo,
                                          int row, int kq, float4 v) {
  unsigned short h0, l0, h1, l1, h2, l2, h3, l3;
  split2(v.x, h0, l0); split2(v.y, h1, l1);
  split2(v.z, h2, l2); split2(v.w, h3, l3);
  uint32_t* ph = (uint32_t*)(hi + row * KSE + kq);
  uint32_t* pl = (uint32_t*)(lo + row * KSE + kq);
  ph[0] = (uint32_t)h0 | ((uint32_t)h1 << 16);
  ph[1] = (uint32_t)h2 | ((uint32_t)h3 << 16);
  pl[0] = (uint32_t)l0 | ((uint32_t)l1 << 16);
  pl[1] = (uint32_t)l2 | ((uint32_t)l3 << 16);
}
__device__ __forceinline__ void store_sp(__nv_bfloat16* hi, __nv_bfloat16* lo,
                                         int row, int k, float x) {
  unsigned short h, l;
  split2(x, h, l);
  hi[row * KSE + k] = __ushort_as_bfloat16(h);
  lo[row * KSE + k] = __ushort_as_bfloat16(l);
}

// Warp-level split-MMA over one KC-wide chunk.
// acc[MI][NI][4]; A rows arow0.. (MI*16), B rows brow0.. (NI*8); 3-combo split.
template <int MI, int NI>
__device__ __forceinline__ void mma_compute(
    float (*acc)[NI][4],
    const __nv_bfloat16* Ah, const __nv_bfloat16* Al,
    const __nv_bfloat16* Bh, const __nv_bfloat16* Bl,
    int arow0, int brow0) {
  int lane = threadIdx.x & 31;
  int g = lane >> 2, tq = (lane & 3) * 2;
  #pragma unroll
  for (int ks = 0; ks < KC; ks += 16) {
    uint32_t ah[MI][4], al[MI][4];
    #pragma unroll
    for (int mi = 0; mi < MI; ++mi) {
      const __nv_bfloat16* p = Ah + (arow0 + mi * 16 + g) * KSE + ks + tq;
      const __nv_bfloat16* q = Al + (arow0 + mi * 16 + g) * KSE + ks + tq;
      ah[mi][0] = *(const uint32_t*)p;
      ah[mi][1] = *(const uint32_t*)(p + 8 * KSE);
      ah[mi][2] = *(const uint32_t*)(p + 8);
      ah[mi][3] = *(const uint32_t*)(p + 8 * KSE + 8);
      al[mi][0] = *(const uint32_t*)q;
      al[mi][1] = *(const uint32_t*)(q + 8 * KSE);
      al[mi][2] = *(const uint32_t*)(q + 8);
      al[mi][3] = *(const uint32_t*)(q + 8 * KSE + 8);
    }
    #pragma unroll
    for (int ni = 0; ni < NI; ++ni) {
      const __nv_bfloat16* p = Bh + (brow0 + ni * 8 + g) * KSE + ks + tq;
      const __nv_bfloat16* q = Bl + (brow0 + ni * 8 + g) * KSE + ks + tq;
      uint32_t bh[2] = { *(const uint32_t*)p, *(const uint32_t*)(p + 8) };
      uint32_t bl[2] = { *(const uint32_t*)q, *(const uint32_t*)(q + 8) };
      #pragma unroll
      for (int mi = 0; mi < MI; ++mi) {
        mma_bf16(acc[mi][ni], ah[mi], bh);
        mma_bf16(acc[mi][ni], al[mi], bh);
        mma_bf16(acc[mi][ni], ah[mi], bl);
      }
    }
  }
}

// ---------------------------------------------------------------------------
// Kernel 1: fused QKV projections. z=(proj,b): C[1024,1024] = X @ Wt.
// ---------------------------------------------------------------------------
__global__ __launch_bounds__(256) void proj_gemm(
    const float* __restrict__ query, const float* __restrict__ key,
    const float* __restrict__ value, const float* __restrict__ w_q,
    const float* __restrict__ w_k,   const float* __restrict__ w_v) {
  extern __shared__ char sm[];
  __nv_bfloat16* Ah = (__nv_bfloat16*)sm;
  __nv_bfloat16* Al = (__nv_bfloat16*)(sm + ATILE);
  __nv_bfloat16* Bh = (__nv_bfloat16*)(sm + 2 * ATILE);
  __nv_bfloat16* Bl = (__nv_bfloat16*)(sm + 3 * ATILE);

  int t = threadIdx.x, w = t >> 5;
  int z = blockIdx.z, proj = z >> 2, b = z & 3;
  const float* X; const float* W; float* OutBase;
  if (proj == 0)      { X = query + (size_t)b * SQ * D; W = w_q; OutBase = g_q; }
  else if (proj == 1) { X = key   + (size_t)b * SK * D; W = w_k; OutBase = g_k; }
  else                { X = value + (size_t)b * SK * D; W = w_v; OutBase = g_v; }

  int m0 = blockIdx.y * 128, n0 = blockIdx.x * 128;
  int h0 = n0 >> 6;
  int wm = w & 1, wn = w >> 1;
  float acc[4][4][4] = {};

  for (int c = 0; c < D / KC; ++c) {
    int k0 = c * KC;
    #pragma unroll
    for (int i = 0; i < 8; ++i) {              // A: 2048 float4
      int f = t + i * 256;
      int r = f >> 4, kq = (f & 15) << 2;
      float4 v = *reinterpret_cast<const float4*>(&X[(size_t)(m0 + r) * D + k0 + kq]);
      store_f4p(Ah, Al, r, kq, v);
    }
    #pragma unroll
    for (int i = 0; i < 8; ++i) {              // B: transposed W load
      int f = t + i * 256;
      int hh = f >> 10, rem = f & 1023;
      int kk = rem >> 4, cq = (rem & 15) << 2;
      float4 v = *reinterpret_cast<const float4*>(
          &W[((size_t)(h0 + hh) * D + (k0 + kk)) * 64 + cq]);
      int n = hh * 64 + cq;
      store_sp(Bh, Bl, n + 0, kk, v.x);
      store_sp(Bh, Bl, n + 1, kk, v.y);
      store_sp(Bh, Bl, n + 2, kk, v.z);
      store_sp(Bh, Bl, n + 3, kk, v.w);
    }
    __syncthreads();
    mma_compute<4, 4>(acc, Ah, Al, Bh, Bl, wm * 64, wn * 32);
    __syncthreads();
  }

  int lane = t & 31, g = lane >> 2, tq = (lane & 3) * 2;
  #pragma unroll
  for (int mi = 0; mi < 4; ++mi) {
    #pragma unroll
    for (int ni = 0; ni < 4; ++ni) {
      int row = m0 + wm * 64 + mi * 16 + g;
      int n   = n0 + wn * 32 + ni * 8 + tq;
      int h = n >> 6, kc = n & 63;
      float* Out = OutBase + ((size_t)(b * H + h) * SQ) * 64 + kc;
      *reinterpret_cast<float2*>(&Out[(size_t)row * 64]) =
          make_float2(acc[mi][ni][0], acc[mi][ni][1]);
      *reinterpret_cast<float2*>(&Out[(size_t)(row + 8) * 64]) =
          make_float2(acc[mi][ni][2], acc[mi][ni][3]);
    }
  }
}

// ---------------------------------------------------------------------------
// Kernel 2: scores = Q @ K^T / 32 (NT, K=64 -> single chunk)
// ---------------------------------------------------------------------------
__global__ __launch_bounds__(256) void scores_gemm(float* __restrict__ attns) {
  extern __shared__ char sm[];
  __nv_bfloat16* Ah = (__nv_bfloat16*)sm;
  __nv_bfloat16* Al = (__nv_bfloat16*)(sm + ATILE);
  __nv_bfloat16* Bh = (__nv_bfloat16*)(sm + 2 * ATILE);
  __nv_bfloat16* Bl = (__nv_bfloat16*)(sm + 3 * ATILE);

  int t = threadIdx.x, w = t >> 5;
  int bh_ = blockIdx.z, b = bh_ / H, h = bh_ % H;
  const float* Qp = g_q + (size_t)bh_ * SQ * DK;
  const float* Kp = g_k + (size_t)bh_ * SK * DK;
  int m0 = blockIdx.y * 128, n0 = blockIdx.x * 128;
  int wm = w & 1, wn = w >> 1;
  float acc[4][4][4] = {};

  #pragma unroll
  for (int i = 0; i < 8; ++i) {
    int f = t + i * 256;
    int r = f >> 4, kq = (f & 15) << 2;
    float4 va = *reinterpret_cast<const float4*>(&Qp[(size_t)(m0 + r) * 64 + kq]);
    store_f4p(Ah, Al, r, kq, va);
    float4 vb = *reinterpret_cast<const float4*>(&Kp[(size_t)(n0 + r) * 64 + kq]);
    store_f4p(Bh, Bl, r, kq, vb);
  }
  __syncthreads();
  mma_compute<4, 4>(acc, Ah, Al, Bh, Bl, wm * 64, wn * 32);

  int lane = t & 31, g = lane >> 2, tq = (lane & 3) * 2;
  float* outbase = attns + (size_t)(h * B + b) * SQ * SK;
  #pragma unroll
  for (int mi = 0; mi < 4; ++mi) {
    #pragma unroll
    for (int ni = 0; ni < 4; ++ni) {
      int row = m0 + wm * 64 + mi * 16 + g;
      int col = n0 + wn * 32 + ni * 8 + tq;
      *reinterpret_cast<float2*>(&outbase[(size_t)row * SK + col]) =
          make_float2(acc[mi][ni][0] * INV_SCALE, acc[mi][ni][1] * INV_SCALE);
      *reinterpret_cast<float2*>(&outbase[(size_t)(row + 8) * SK + col]) =
          make_float2(acc[mi][ni][2] * INV_SCALE, acc[mi][ni][3] * INV_SCALE);
    }
  }
}

// ---------------------------------------------------------------------------
// Kernel 3: in-place row softmax. 1 block per row.
// ---------------------------------------------------------------------------
__global__ __launch_bounds__(256) void softmax_kernel(float* __restrict__ attns) {
  __shared__ float redm[8];
  __shared__ float reds[8];
  float* p = attns + (size_t)blockIdx.x * SK;
  int tid = threadIdx.x;

  float4 v = reinterpret_cast<float4*>(p)[tid];
  float mx = fmaxf(fmaxf(v.x, v.y), fmaxf(v.z, v.w));
  #pragma unroll
  for (int o = 16; o > 0; o >>= 1) mx = fmaxf(mx, __shfl_xor_sync(0xffffffffu, mx, o));
  if ((tid & 31) == 0) redm[tid >> 5] = mx;
  __syncthreads();
  float m_all = redm[0];
  #pragma unroll
  for (int i = 1; i < 8; ++i) m_all = fmaxf(m_all, redm[i]);

  v.x = __expf(v.x - m_all); v.y = __expf(v.y - m_all);
  v.z = __expf(v.z - m_all); v.w = __expf(v.w - m_all);
  float s = v.x + v.y + v.z + v.w;
  #pragma unroll
  for (int o = 16; o > 0; o >>= 1) s += __shfl_xor_sync(0xffffffffu, s, o);
  if ((tid & 31) == 0) reds[tid >> 5] = s;
  __syncthreads();
  float s_all = 0.f;
  #pragma unroll
  for (int i = 0; i < 8; ++i) s_all += reds[i];
  float inv = 1.0f / s_all;

  v.x *= inv; v.y *= inv; v.z *= inv; v.w *= inv;
  reinterpret_cast<float4*>(p)[tid] = v;
}

// ---------------------------------------------------------------------------
// Kernel 4: ctx = P @ V (NT with B = V^T built on the fly). M=1024, N=64, K=1024.
// Block tile 128 x 64; 8 warps as 4(m) x 2(n) -> warp 32x32 (MI=2, NI=4).
// ---------------------------------------------------------------------------
__global__ __launch_bounds__(256) void av_gemm(const float* __restrict__ attns) {
  extern __shared__ char sm[];
  __nv_bfloat16* Ah = (__nv_bfloat16*)sm;
  __nv_bfloat16* Al = (__nv_bfloat16*)(sm + ATILE);
  __nv_bfloat16* Bh = (__nv_bfloat16*)(sm + 2 * ATILE);
  __nv_bfloat16* Bl = (__nv_bfloat16*)(sm + 2 * ATILE + BTILE64);

  int t = threadIdx.x, w = t >> 5;
  int bh_ = blockIdx.z, b = bh_ / H, h = bh_ % H;
  const float* A = attns + (size_t)(h * B + b) * SQ * SK;
  const float* V = g_v + (size_t)bh_ * SK * DV;
  int m0 = blockIdx.y * 128;
  int wm = w >> 1, wn = w & 1;
  float acc[2][4][4] = {};

  for (int c = 0; c < SK / KC; ++c) {
    int k0 = c * KC;
    #pragma unroll
    for (int i = 0; i < 8; ++i) {              // A: 2048 float4
      int f = t + i * 256;
      int r = f >> 4, kq = (f & 15) << 2;
      float4 v = *reinterpret_cast<const float4*>(&A[(size_t)(m0 + r) * SK + k0 + kq]);
      store_f4p(Ah, Al, r, kq, v);
    }
    #pragma unroll
    for (int i = 0; i < 4; ++i) {              // B = V^T: 1024 float4
      int f = t + i * 256;
      int kk = f >> 4, nq = (f & 15) << 2;
      float4 v = *reinterpret_cast<const float4*>(&V[(size_t)(k0 + kk) * 64 + nq]);
      store_sp(Bh, Bl, nq + 0, kk, v.x);
      store_sp(Bh, Bl, nq + 1, kk, v.y);
      store_sp(Bh, Bl, nq + 2, kk, v.z);
      store_sp(Bh, Bl, nq + 3, kk, v.w);
    }
    __syncthreads();
    mma_compute<2, 4>(acc, Ah, Al, Bh, Bl, wm * 32, wn * 32);
    __syncthreads();
  }

  int lane = t & 31, g = lane >> 2, tq = (lane & 3) * 2;
  #pragma unroll
  for (int mi = 0; mi < 2; ++mi) {
    #pragma unroll
    for (int ni = 0; ni < 4; ++ni) {
      int row = m0 + wm * 32 + mi * 16 + g;
      int col = wn * 32 + ni * 8 + tq;
      float* o0 = &g_ctx[(((size_t)b * SQ + row) * H + h) * 64 + col];
      float* o1 = &g_ctx[(((size_t)b * SQ + row + 8) * H + h) * 64 + col];
      *reinterpret_cast<float2*>(o0) = make_float2(acc[mi][ni][0], acc[mi][ni][1]);
      *reinterpret_cast<float2*>(o1) = make_float2(acc[mi][ni][2], acc[mi][ni][3]);
    }
  }
}

// ---------------------------------------------------------------------------
// Kernel 5: out = ctx @ w_proj^T + b_proj (NT). M=4096, N=1024, K=1024.
// ---------------------------------------------------------------------------
__global__ __launch_bounds__(256) void outproj_gemm(
    const float* __restrict__ w_proj, const float* __restrict__ b_proj,
    float* __restrict__ out) {
  extern __shared__ char sm[];
  __nv_bfloat16* Ah = (__nv_bfloat16*)sm;
  __nv_bfloat16* Al = (__nv_bfloat16*)(sm + ATILE);
  __nv_bfloat16* Bh = (__nv_bfloat16*)(sm + 2 * ATILE);
  __nv_bfloat16* Bl = (__nv_bfloat16*)(sm + 3 * ATILE);

  int t = threadIdx.x, w = t >> 5;
  const int K = H * DV;
  int m0 = blockIdx.y * 128, n0 = blockIdx.x * 128;
  int wm = w & 1, wn = w >> 1;
  float acc[4][4][4] = {};

  for (int c = 0; c < K / KC; ++c) {
    int k0 = c * KC;
    #pragma unroll
    for (int i = 0; i < 8; ++i) {
      int f = t + i * 256;
      int r = f >> 4, kq = (f & 15) << 2;
      float4 va = *reinterpret_cast<const float4*>(&g_ctx[(size_t)(m0 + r) * K + k0 + kq]);
      store_f4p(Ah, Al, r, kq, va);
      float4 vb = *reinterpret_cast<const float4*>(&w_proj[(size_t)(n0 + r) * K + k0 + kq]);
      store_f4p(Bh, Bl, r, kq, vb);
    }
    __syncthreads();
    mma_compute<4, 4>(acc, Ah, Al, Bh, Bl, wm * 64, wn * 32);
    __syncthreads();
  }

  int lane = t & 31, g = lane >> 2, tq = (lane & 3) * 2;
  #pragma unroll
  for (int mi = 0; mi < 4; ++mi) {
    #pragma unroll
    for (int ni = 0; ni < 4; ++ni) {
      int row = m0 + wm * 64 + mi * 16 + g;
      int col = n0 + wn * 32 + ni * 8 + tq;
      float2 bb = *reinterpret_cast<const float2*>(&b_proj[col]);
      *reinterpret_cast<float2*>(&out[(size_t)row * D + col]) =
          make_float2(acc[mi][ni][0] + bb.x, acc[mi][ni][1] + bb.y);
      *reinterpret_cast<float2*>(&out[(size_t)(row + 8) * D + col]) =
          make_float2(acc[mi][ni][2] + bb.x, acc[mi][ni][3] + bb.y);
    }
  }
}

// ---------------------------------------------------------------------------
extern "C" void kernel_launch(void* const* d_in, const int* in_sizes, int n_in,
                              void* d_out, int out_size) {
  const float* query  = (const float*)d_in[0];
  const float* key    = (const float*)d_in[1];
  const float* value  = (const float*)d_in[2];
  const float* w_q    = (const float*)d_in[3];
  const float* w_k    = (const float*)d_in[4];
  const float* w_v    = (const float*)d_in[5];
  const float* w_proj = (const float*)d_in[6];
  const float* b_proj = (const float*)d_in[7];

  float* out   = (float*)d_out;
  float* attns = out + (size_t)B * SQ * D;

  static bool attr_done = false;
  if (!attr_done) {
    cudaFuncSetAttribute(proj_gemm,    cudaFuncAttributeMaxDynamicSharedMemorySize, SMEM_BIG);
    cudaFuncSetAttribute(scores_gemm,  cudaFuncAttributeMaxDynamicSharedMemorySize, SMEM_BIG);
    cudaFuncSetAttribute(av_gemm,      cudaFuncAttributeMaxDynamicSharedMemorySize, SMEM_AV);
    cudaFuncSetAttribute(outproj_gemm, cudaFuncAttributeMaxDynamicSharedMemorySize, SMEM_BIG);
    attr_done = true;
  }

  proj_gemm<<<dim3(8, 8, 12), 256, SMEM_BIG>>>(query, key, value, w_q, w_k, w_v);
  scores_gemm<<<dim3(8, 8, B * H), 256, SMEM_BIG>>>(attns);
  softmax_kernel<<<H * B * SQ, 256>>>(attns);
  av_gemm<<<dim3(1, 8, B * H), 256, SMEM_AV>>>(attns);
  outproj_gemm<<<dim3(8, 32, 1), 256, SMEM_BIG>>>(w_proj, b_proj, out);
}

// round 6
// speedup vs baseline: 2.1448x; 2.1448x over previous
#include <cuda_runtime.h>
#include <cuda_bf16.h>
#include <cstdint>

namespace {
constexpr int H  = 16;
constexpr int D  = 1024;
constexpr int B  = 4;
constexpr int SQ = 1024;
constexpr int SK = 1024;
constexpr float INV_SCALE = 1.0f / 32.0f;   // 1/sqrt(1024)

constexpr int KSE   = 72;                    // smem row stride (bf16 elems); 144B
constexpr int TBA   = 128 * KSE * 2;         // 18432 B (128-row tile)
constexpr int TBB64 = 64 * KSE * 2;          // 9216 B  (64-row tile)
constexpr int STAGE_BIG = 4 * TBA;           // Ahi,Alo,Bhi,Blo
constexpr int SMEM_PIPE = 2 * STAGE_BIG;     // 147456
constexpr int STAGE_AV  = 2 * TBA + 2 * TBB64;
constexpr int SMEM_AVP  = 2 * STAGE_AV;      // 110592
constexpr int SMEM_SC   = STAGE_BIG;         // scores: single stage
}

// ------------------------- global scratch (bf16 hi/lo) ----------------------
__device__ __nv_bfloat16 g_xhi[3u * 4 * 1024 * 1024];
__device__ __nv_bfloat16 g_xlo[3u * 4 * 1024 * 1024];
__device__ __nv_bfloat16 g_wthi[3u * 1024 * 1024];   // [p][n=h*64+c][d]
__device__ __nv_bfloat16 g_wtlo[3u * 1024 * 1024];
__device__ __nv_bfloat16 g_qhi[64u * 1024 * 64];     // [bh][s][k]
__device__ __nv_bfloat16 g_qlo[64u * 1024 * 64];
__device__ __nv_bfloat16 g_khi[64u * 1024 * 64];
__device__ __nv_bfloat16 g_klo[64u * 1024 * 64];
__device__ __nv_bfloat16 g_vthi[64u * 64 * 1024];    // [bh][v][s]
__device__ __nv_bfloat16 g_vtlo[64u * 64 * 1024];
__device__ __nv_bfloat16 g_phi[64u * 1024 * 1024];   // [h*B+b][q][s]
__device__ __nv_bfloat16 g_plo[64u * 1024 * 1024];
__device__ __nv_bfloat16 g_ctxhi[4096u * 1024];      // [b*q][h*64+v]
__device__ __nv_bfloat16 g_ctxlo[4096u * 1024];
__device__ __nv_bfloat16 g_wphi[1024u * 1024];       // [n][k]
__device__ __nv_bfloat16 g_wplo[1024u * 1024];

// ------------------------------ helpers -------------------------------------
__device__ __forceinline__ uint32_t cvta_s(const void* p) {
  uint32_t a;
  asm("{ .reg .u64 t; cvta.to.shared.u64 t, %1; cvt.u32.u64 %0, t; }" : "=r"(a) : "l"(p));
  return a;
}
__device__ __forceinline__ void cp16(uint32_t d, const void* s) {
  asm volatile("cp.async.ca.shared.global [%0], [%1], 16;" :: "r"(d), "l"(s));
}
__device__ __forceinline__ void cp_commit() { asm volatile("cp.async.commit_group;" ::: "memory"); }
__device__ __forceinline__ void cp_wait0()  { asm volatile("cp.async.wait_group 0;" ::: "memory"); }
__device__ __forceinline__ void cp_wait1()  { asm volatile("cp.async.wait_group 1;" ::: "memory"); }

__device__ __forceinline__ void ldm4(uint32_t& r0, uint32_t& r1, uint32_t& r2, uint32_t& r3,
                                     uint32_t a) {
  asm volatile("ldmatrix.sync.aligned.m8n8.x4.shared.b16 {%0,%1,%2,%3}, [%4];"
               : "=r"(r0), "=r"(r1), "=r"(r2), "=r"(r3) : "r"(a));
}
__device__ __forceinline__ void mma_bf16(float* c, const uint32_t* a, uint32_t b0, uint32_t b1) {
  asm volatile(
      "mma.sync.aligned.m16n8k16.row.col.f32.bf16.bf16.f32 "
      "{%0,%1,%2,%3}, {%4,%5,%6,%7}, {%8,%9}, {%0,%1,%2,%3};"
      : "+f"(c[0]), "+f"(c[1]), "+f"(c[2]), "+f"(c[3])
      : "r"(a[0]), "r"(a[1]), "r"(a[2]), "r"(a[3]), "r"(b0), "r"(b1));
}

__device__ __forceinline__ void split_pack(float a, float b, uint32_t& hi, uint32_t& lo) {
  __nv_bfloat16 h0 = __float2bfloat16(a), h1 = __float2bfloat16(b);
  __nv_bfloat16 l0 = __float2bfloat16(a - __bfloat162float(h0));
  __nv_bfloat16 l1 = __float2bfloat16(b - __bfloat162float(h1));
  hi = (uint32_t)__bfloat16_as_ushort(h0) | ((uint32_t)__bfloat16_as_ushort(h1) << 16);
  lo = (uint32_t)__bfloat16_as_ushort(l0) | ((uint32_t)__bfloat16_as_ushort(l1) << 16);
}

// fill a 128-row x 64-k bf16 tile via cp.async (1024 16B chunks, 256 threads)
__device__ __forceinline__ void fill128(uint32_t sbase, const __nv_bfloat16* g,
                                        int rstride, int t) {
  #pragma unroll
  for (int i = 0; i < 4; ++i) {
    int f = t + i * 256;
    int r = f >> 3, ck = (f & 7) * 8;
    cp16(sbase + (uint32_t)(r * KSE + ck) * 2, g + (size_t)r * rstride + ck);
  }
}
__device__ __forceinline__ void fill64(uint32_t sbase, const __nv_bfloat16* g,
                                       int rstride, int t) {
  #pragma unroll
  for (int i = 0; i < 2; ++i) {
    int f = t + i * 256;
    int r = f >> 3, ck = (f & 7) * 8;
    cp16(sbase + (uint32_t)(r * KSE + ck) * 2, g + (size_t)r * rstride + ck);
  }
}

// split 3-term MMA over one 64-k chunk. acc[MI][4][4], warp tile MI*16 x 32.
template <int MI>
__device__ __forceinline__ void mma_tile(float (*acc)[4][4],
                                         uint32_t sAh, uint32_t sAl,
                                         uint32_t sBh, uint32_t sBl,
                                         int arow0, int brow0) {
  int lane = threadIdx.x & 31;
  int lr = lane & 15, lh = lane >> 4;
  #pragma unroll
  for (int ks = 0; ks < 64; ks += 16) {
    int ko = ks + lh * 8;
    uint32_t ah[MI][4], al[MI][4];
    #pragma unroll
    for (int mi = 0; mi < MI; ++mi) {
      uint32_t off = (uint32_t)((arow0 + mi * 16 + lr) * KSE + ko) * 2;
      ldm4(ah[mi][0], ah[mi][1], ah[mi][2], ah[mi][3], sAh + off);
      ldm4(al[mi][0], al[mi][1], al[mi][2], al[mi][3], sAl + off);
    }
    uint32_t bh[2][4], bl[2][4];
    #pragma unroll
    for (int np = 0; np < 2; ++np) {
      uint32_t off = (uint32_t)((brow0 + np * 16 + lr) * KSE + ko) * 2;
      ldm4(bh[np][0], bh[np][1], bh[np][2], bh[np][3], sBh + off);
      ldm4(bl[np][0], bl[np][1], bl[np][2], bl[np][3], sBl + off);
    }
    #pragma unroll
    for (int mi = 0; mi < MI; ++mi) {
      #pragma unroll
      for (int np = 0; np < 2; ++np) {
        mma_bf16(acc[mi][2 * np],     ah[mi], bh[np][0], bh[np][2]);
        mma_bf16(acc[mi][2 * np],     al[mi], bh[np][0], bh[np][2]);
        mma_bf16(acc[mi][2 * np],     ah[mi], bl[np][0], bl[np][2]);
        mma_bf16(acc[mi][2 * np + 1], ah[mi], bh[np][1], bh[np][3]);
        mma_bf16(acc[mi][2 * np + 1], al[mi], bh[np][1], bh[np][3]);
        mma_bf16(acc[mi][2 * np + 1], ah[mi], bl[np][1], bl[np][3]);
      }
    }
  }
}

// -------------------------- pre-pass conversions ----------------------------
__global__ __launch_bounds__(256) void conv_x(const float* __restrict__ query,
                                              const float* __restrict__ key,
                                              const float* __restrict__ value) {
  int p = blockIdx.y;
  const float* src = (p == 0) ? query : (p == 1) ? key : value;
  size_t i = ((size_t)blockIdx.x * 256 + threadIdx.x) * 4;
  float4 v = *reinterpret_cast<const float4*>(src + i);
  size_t o = (size_t)p * 4 * 1024 * 1024 + i;
  uint32_t h0, l0, h1, l1;
  split_pack(v.x, v.y, h0, l0);
  split_pack(v.z, v.w, h1, l1);
  *(uint32_t*)(g_xhi + o)     = h0;  *(uint32_t*)(g_xhi + o + 2) = h1;
  *(uint32_t*)(g_xlo + o)     = l0;  *(uint32_t*)(g_xlo + o + 2) = l1;
}

__global__ __launch_bounds__(256) void conv_w(const float* __restrict__ w_q,
                                              const float* __restrict__ w_k,
                                              const float* __restrict__ w_v) {
  int p = blockIdx.y, n = blockIdx.x;
  const float* W = (p == 0) ? w_q : (p == 1) ? w_k : w_v;
  int h = n >> 6, c = n & 63;
  int d0 = threadIdx.x * 4;
  float a = W[(size_t)h * 65536 + (size_t)(d0 + 0) * 64 + c];
  float b = W[(size_t)h * 65536 + (size_t)(d0 + 1) * 64 + c];
  float e = W[(size_t)h * 65536 + (size_t)(d0 + 2) * 64 + c];
  float f = W[(size_t)h * 65536 + (size_t)(d0 + 3) * 64 + c];
  size_t o = ((size_t)p * 1024 + n) * 1024 + d0;
  uint32_t h0, l0, h1, l1;
  split_pack(a, b, h0, l0);
  split_pack(e, f, h1, l1);
  *(uint32_t*)(g_wthi + o)     = h0;  *(uint32_t*)(g_wthi + o + 2) = h1;
  *(uint32_t*)(g_wtlo + o)     = l0;  *(uint32_t*)(g_wtlo + o + 2) = l1;
}

__global__ __launch_bounds__(256) void conv_wp(const float* __restrict__ w_proj) {
  int n = blockIdx.x;
  int k0 = threadIdx.x * 4;
  float4 v = *reinterpret_cast<const float4*>(w_proj + (size_t)n * 1024 + k0);
  size_t o = (size_t)n * 1024 + k0;
  uint32_t h0, l0, h1, l1;
  split_pack(v.x, v.y, h0, l0);
  split_pack(v.z, v.w, h1, l1);
  *(uint32_t*)(g_wphi + o)     = h0;  *(uint32_t*)(g_wphi + o + 2) = h1;
  *(uint32_t*)(g_wplo + o)     = l0;  *(uint32_t*)(g_wplo + o + 2) = l1;
}

// ------------------------------ GEMM kernels --------------------------------
__global__ __launch_bounds__(256) void proj_gemm() {
  extern __shared__ char sm[];
  int t = threadIdx.x, w = t >> 5, lane = t & 31;
  int z = blockIdx.z, p = z >> 2, b = z & 3;
  int m0 = blockIdx.y * 128, n0 = blockIdx.x * 128;

  const __nv_bfloat16* Ah_g = g_xhi + ((size_t)p * 4 + b) * SQ * D + (size_t)m0 * D;
  const __nv_bfloat16* Al_g = g_xlo + ((size_t)p * 4 + b) * SQ * D + (size_t)m0 * D;
  const __nv_bfloat16* Bh_g = g_wthi + (size_t)p * 1024 * 1024 + (size_t)n0 * 1024;
  const __nv_bfloat16* Bl_g = g_wtlo + (size_t)p * 1024 * 1024 + (size_t)n0 * 1024;

  uint32_t sb0 = cvta_s(sm);
  int wm = w & 1, wn = w >> 1;
  float acc[4][4][4] = {};

  // prologue
  {
    uint32_t s = sb0;
    fill128(s,           Ah_g, D,    t);
    fill128(s + TBA,     Al_g, D,    t);
    fill128(s + 2 * TBA, Bh_g, 1024, t);
    fill128(s + 3 * TBA, Bl_g, 1024, t);
    cp_commit();
  }
  for (int c = 0; c < 16; ++c) {
    if (c + 1 < 16) {
      uint32_t s = sb0 + ((c + 1) & 1) * STAGE_BIG;
      int k0 = (c + 1) * 64;
      fill128(s,           Ah_g + k0, D,    t);
      fill128(s + TBA,     Al_g + k0, D,    t);
      fill128(s + 2 * TBA, Bh_g + k0, 1024, t);
      fill128(s + 3 * TBA, Bl_g + k0, 1024, t);
      cp_commit();
      cp_wait1();
    } else {
      cp_wait0();
    }
    __syncthreads();
    uint32_t s = sb0 + (c & 1) * STAGE_BIG;
    mma_tile<4>(acc, s, s + TBA, s + 2 * TBA, s + 3 * TBA, wm * 64, wn * 32);
    __syncthreads();
  }

  int g = lane >> 2, tq = (lane & 3) * 2;
  if (p < 2) {
    __nv_bfloat16* Hi = (p == 0) ? g_qhi : g_khi;
    __nv_bfloat16* Lo = (p == 0) ? g_qlo : g_klo;
    #pragma unroll
    for (int mi = 0; mi < 4; ++mi)
      #pragma unroll
      for (int ni = 0; ni < 4; ++ni) {
        int row = m0 + wm * 64 + mi * 16 + g;
        int col = n0 + wn * 32 + ni * 8 + tq;
        int h = col >> 6, kc = col & 63;
        size_t o0 = ((size_t)(b * H + h) * 1024 + row) * 64 + kc;
        size_t o1 = ((size_t)(b * H + h) * 1024 + row + 8) * 64 + kc;
        uint32_t hv, lv;
        split_pack(acc[mi][ni][0], acc[mi][ni][1], hv, lv);
        *(uint32_t*)(Hi + o0) = hv; *(uint32_t*)(Lo + o0) = lv;
        split_pack(acc[mi][ni][2], acc[mi][ni][3], hv, lv);
        *(uint32_t*)(Hi + o1) = hv; *(uint32_t*)(Lo + o1) = lv;
      }
  } else {
    // V: write transposed [bh][v][s]
    #pragma unroll
    for (int mi = 0; mi < 4; ++mi)
      #pragma unroll
      for (int ni = 0; ni < 4; ++ni) {
        int row = m0 + wm * 64 + mi * 16 + g;
        int col = n0 + wn * 32 + ni * 8 + tq;
        int h = col >> 6, kc = col & 63;
        size_t base = (size_t)(b * H + h) * 64 * 1024;
        #pragma unroll
        for (int j = 0; j < 4; ++j) {
          int v = kc + (j & 1);
          int srow = row + (j >> 1) * 8;
          float x = acc[mi][ni][j];
          __nv_bfloat16 hb = __float2bfloat16(x);
          g_vthi[base + (size_t)v * 1024 + srow] = hb;
          g_vtlo[base + (size_t)v * 1024 + srow] =
              __float2bfloat16(x - __bfloat162float(hb));
        }
      }
  }
}

__global__ __launch_bounds__(256) void scores_gemm(float* __restrict__ attns) {
  extern __shared__ char sm[];
  int t = threadIdx.x, w = t >> 5, lane = t & 31;
  int z = blockIdx.z, b = z >> 4, h = z & 15;
  int m0 = blockIdx.y * 128, n0 = blockIdx.x * 128;

  const __nv_bfloat16* Ah_g = g_qhi + (size_t)z * 1024 * 64 + (size_t)m0 * 64;
  const __nv_bfloat16* Al_g = g_qlo + (size_t)z * 1024 * 64 + (size_t)m0 * 64;
  const __nv_bfloat16* Bh_g = g_khi + (size_t)z * 1024 * 64 + (size_t)n0 * 64;
  const __nv_bfloat16* Bl_g = g_klo + (size_t)z * 1024 * 64 + (size_t)n0 * 64;

  uint32_t s = cvta_s(sm);
  fill128(s,           Ah_g, 64, t);
  fill128(s + TBA,     Al_g, 64, t);
  fill128(s + 2 * TBA, Bh_g, 64, t);
  fill128(s + 3 * TBA, Bl_g, 64, t);
  cp_commit();
  cp_wait0();
  __syncthreads();

  int wm = w & 1, wn = w >> 1;
  float acc[4][4][4] = {};
  mma_tile<4>(acc, s, s + TBA, s + 2 * TBA, s + 3 * TBA, wm * 64, wn * 32);

  int g = lane >> 2, tq = (lane & 3) * 2;
  float* outb = attns + (size_t)(h * B + b) * SQ * SK;
  #pragma unroll
  for (int mi = 0; mi < 4; ++mi)
    #pragma unroll
    for (int ni = 0; ni < 4; ++ni) {
      int row = m0 + wm * 64 + mi * 16 + g;
      int col = n0 + wn * 32 + ni * 8 + tq;
      *reinterpret_cast<float2*>(&outb[(size_t)row * SK + col]) =
          make_float2(acc[mi][ni][0] * INV_SCALE, acc[mi][ni][1] * INV_SCALE);
      *reinterpret_cast<float2*>(&outb[(size_t)(row + 8) * SK + col]) =
          make_float2(acc[mi][ni][2] * INV_SCALE, acc[mi][ni][3] * INV_SCALE);
    }
}

__global__ __launch_bounds__(256) void softmax_kernel(float* __restrict__ attns) {
  __shared__ float redm[8];
  __shared__ float reds[8];
  size_t rb = (size_t)blockIdx.x * SK;
  float* p = attns + rb;
  int tid = threadIdx.x;

  float4 v = reinterpret_cast<float4*>(p)[tid];
  float mx = fmaxf(fmaxf(v.x, v.y), fmaxf(v.z, v.w));
  #pragma unroll
  for (int o = 16; o > 0; o >>= 1) mx = fmaxf(mx, __shfl_xor_sync(0xffffffffu, mx, o));
  if ((tid & 31) == 0) redm[tid >> 5] = mx;
  __syncthreads();
  float m_all = redm[0];
  #pragma unroll
  for (int i = 1; i < 8; ++i) m_all = fmaxf(m_all, redm[i]);

  v.x = __expf(v.x - m_all); v.y = __expf(v.y - m_all);
  v.z = __expf(v.z - m_all); v.w = __expf(v.w - m_all);
  float s = v.x + v.y + v.z + v.w;
  #pragma unroll
  for (int o = 16; o > 0; o >>= 1) s += __shfl_xor_sync(0xffffffffu, s, o);
  if ((tid & 31) == 0) reds[tid >> 5] = s;
  __syncthreads();
  float s_all = 0.f;
  #pragma unroll
  for (int i = 0; i < 8; ++i) s_all += reds[i];
  float inv = 1.0f / s_all;

  v.x *= inv; v.y *= inv; v.z *= inv; v.w *= inv;
  reinterpret_cast<float4*>(p)[tid] = v;

  uint32_t h0, l0, h1, l1;
  split_pack(v.x, v.y, h0, l0);
  split_pack(v.z, v.w, h1, l1);
  size_t o = rb + (size_t)tid * 4;
  *(uint32_t*)(g_phi + o)     = h0;  *(uint32_t*)(g_phi + o + 2) = h1;
  *(uint32_t*)(g_plo + o)     = l0;  *(uint32_t*)(g_plo + o + 2) = l1;
}

__global__ __launch_bounds__(256) void av_gemm() {
  extern __shared__ char sm[];
  int t = threadIdx.x, w = t >> 5, lane = t & 31;
  int z = blockIdx.z, b = z >> 4, h = z & 15;
  int m0 = blockIdx.y * 128;

  const __nv_bfloat16* Ah_g = g_phi + (size_t)(h * B + b) * SQ * SK + (size_t)m0 * SK;
  const __nv_bfloat16* Al_g = g_plo + (size_t)(h * B + b) * SQ * SK + (size_t)m0 * SK;
  const __nv_bfloat16* Bh_g = g_vthi + (size_t)z * 64 * 1024;
  const __nv_bfloat16* Bl_g = g_vtlo + (size_t)z * 64 * 1024;

  uint32_t sb0 = cvta_s(sm);
  int wm = w >> 1, wn = w & 1;
  float acc[2][4][4] = {};

  {
    uint32_t s = sb0;
    fill128(s,                 Ah_g, 1024, t);
    fill128(s + TBA,           Al_g, 1024, t);
    fill64 (s + 2 * TBA,         Bh_g, 1024, t);
    fill64 (s + 2 * TBA + TBB64, Bl_g, 1024, t);
    cp_commit();
  }
  for (int c = 0; c < 16; ++c) {
    if (c + 1 < 16) {
      uint32_t s = sb0 + ((c + 1) & 1) * STAGE_AV;
      int k0 = (c + 1) * 64;
      fill128(s,                 Ah_g + k0, 1024, t);
      fill128(s + TBA,           Al_g + k0, 1024, t);
      fill64 (s + 2 * TBA,         Bh_g + k0, 1024, t);
      fill64 (s + 2 * TBA + TBB64, Bl_g + k0, 1024, t);
      cp_commit();
      cp_wait1();
    } else {
      cp_wait0();
    }
    __syncthreads();
    uint32_t s = sb0 + (c & 1) * STAGE_AV;
    mma_tile<2>(acc, s, s + TBA, s + 2 * TBA, s + 2 * TBA + TBB64, wm * 32, wn * 32);
    __syncthreads();
  }

  int g = lane >> 2, tq = (lane & 3) * 2;
  #pragma unroll
  for (int mi = 0; mi < 2; ++mi)
    #pragma unroll
    for (int ni = 0; ni < 4; ++ni) {
      int row = m0 + wm * 32 + mi * 16 + g;
      int col = wn * 32 + ni * 8 + tq;
      size_t o0 = ((size_t)b * 1024 + row) * 1024 + h * 64 + col;
      size_t o1 = ((size_t)b * 1024 + row + 8) * 1024 + h * 64 + col;
      uint32_t hv, lv;
      split_pack(acc[mi][ni][0], acc[mi][ni][1], hv, lv);
      *(uint32_t*)(g_ctxhi + o0) = hv; *(uint32_t*)(g_ctxlo + o0) = lv;
      split_pack(acc[mi][ni][2], acc[mi][ni][3], hv, lv);
      *(uint32_t*)(g_ctxhi + o1) = hv; *(uint32_t*)(g_ctxlo + o1) = lv;
    }
}

__global__ __launch_bounds__(256) void outproj_gemm(const float* __restrict__ b_proj,
                                                    float* __restrict__ out) {
  extern __shared__ char sm[];
  int t = threadIdx.x, w = t >> 5, lane = t & 31;
  int m0 = blockIdx.y * 128, n0 = blockIdx.x * 128;

  const __nv_bfloat16* Ah_g = g_ctxhi + (size_t)m0 * 1024;
  const __nv_bfloat16* Al_g = g_ctxlo + (size_t)m0 * 1024;
  const __nv_bfloat16* Bh_g = g_wphi + (size_t)n0 * 1024;
  const __nv_bfloat16* Bl_g = g_wplo + (size_t)n0 * 1024;

  uint32_t sb0 = cvta_s(sm);
  int wm = w & 1, wn = w >> 1;
  float acc[4][4][4] = {};

  {
    uint32_t s = sb0;
    fill128(s,           Ah_g, 1024, t);
    fill128(s + TBA,     Al_g, 1024, t);
    fill128(s + 2 * TBA, Bh_g, 1024, t);
    fill128(s + 3 * TBA, Bl_g, 1024, t);
    cp_commit();
  }
  for (int c = 0; c < 16; ++c) {
    if (c + 1 < 16) {
      uint32_t s = sb0 + ((c + 1) & 1) * STAGE_BIG;
      int k0 = (c + 1) * 64;
      fill128(s,           Ah_g + k0, 1024, t);
      fill128(s + TBA,     Al_g + k0, 1024, t);
      fill128(s + 2 * TBA, Bh_g + k0, 1024, t);
      fill128(s + 3 * TBA, Bl_g + k0, 1024, t);
      cp_commit();
      cp_wait1();
    } else {
      cp_wait0();
    }
    __syncthreads();
    uint32_t s = sb0 + (c & 1) * STAGE_BIG;
    mma_tile<4>(acc, s, s + TBA, s + 2 * TBA, s + 3 * TBA, wm * 64, wn * 32);
    __syncthreads();
  }

  int g = lane >> 2, tq = (lane & 3) * 2;
  #pragma unroll
  for (int mi = 0; mi < 4; ++mi)
    #pragma unroll
    for (int ni = 0; ni < 4; ++ni) {
      int row = m0 + wm * 64 + mi * 16 + g;
      int col = n0 + wn * 32 + ni * 8 + tq;
      float2 bb = *reinterpret_cast<const float2*>(&b_proj[col]);
      *reinterpret_cast<float2*>(&out[(size_t)row * D + col]) =
          make_float2(acc[mi][ni][0] + bb.x, acc[mi][ni][1] + bb.y);
      *reinterpret_cast<float2*>(&out[(size_t)(row + 8) * D + col]) =
          make_float2(acc[mi][ni][2] + bb.x, acc[mi][ni][3] + bb.y);
    }
}

// ---------------------------------------------------------------------------
extern "C" void kernel_launch(void* const* d_in, const int* in_sizes, int n_in,
                              void* d_out, int out_size) {
  const float* query  = (const float*)d_in[0];
  const float* key    = (const float*)d_in[1];
  const float* value  = (const float*)d_in[2];
  const float* w_q    = (const float*)d_in[3];
  const float* w_k    = (const float*)d_in[4];
  const float* w_v    = (const float*)d_in[5];
  const float* w_proj = (const float*)d_in[6];
  const float* b_proj = (const float*)d_in[7];

  float* out   = (float*)d_out;
  float* attns = out + (size_t)B * SQ * D;

  static bool attr_done = false;
  if (!attr_done) {
    cudaFuncSetAttribute(proj_gemm,    cudaFuncAttributeMaxDynamicSharedMemorySize, SMEM_PIPE);
    cudaFuncSetAttribute(scores_gemm,  cudaFuncAttributeMaxDynamicSharedMemorySize, SMEM_SC);
    cudaFuncSetAttribute(av_gemm,      cudaFuncAttributeMaxDynamicSharedMemorySize, SMEM_AVP);
    cudaFuncSetAttribute(outproj_gemm, cudaFuncAttributeMaxDynamicSharedMemorySize, SMEM_PIPE);
    attr_done = true;
  }

  conv_x <<<dim3(4096, 3), 256>>>(query, key, value);
  conv_w <<<dim3(1024, 3), 256>>>(w_q, w_k, w_v);
  conv_wp<<<dim3(1024, 1), 256>>>(w_proj);

  proj_gemm   <<<dim3(8, 8, 12),      256, SMEM_PIPE>>>();
  scores_gemm <<<dim3(8, 8, 64),      256, SMEM_SC>>>(attns);
  softmax_kernel<<<H * B * SQ, 256>>>(attns);
  av_gemm     <<<dim3(1, 8, 64),      256, SMEM_AVP>>>();
  outproj_gemm<<<dim3(8, 32, 1),      256, SMEM_PIPE>>>(b_proj, out);
}